// round 10
// baseline (speedup 1.0000x reference)
#include <cuda_runtime.h>
#include <stdint.h>

// Segmented max pooling — bucketed gather:
//   1) zero:   counts + spill counter (1 MB)
//   2) fill:   pos = atomicAdd(count[seg]); pos<CAP -> bucket, else spill list
//   3) gather: 1 warp per 4 segments, batched predicated loads (MLP=16),
//              int4 bucket/count loads, inline spill scan.
//
// LESSONS BAKED IN:
//  - No single-address done-counter atomic (R6/R7: +400us, LTS convoy).
//  - Plain __ldg loads (measured good R5/R8).
//  - MLP is the gather lever: 4->8 loads/warp bought 10us (R9).
// Fallback: generic atomic-scatter path for shapes beyond static scratch.

#define MAX_SEG   (1 << 18)   // 262144
#define MAX_ROWS  (1 << 20)   // 1048576
#define CAP        16
#define NEG_INF __int_as_float(0xff800000)

__device__ int g_counts[MAX_SEG];
__device__ int g_bucket[MAX_SEG * CAP];   // 16 MB scratch
__device__ int g_spill_rows[MAX_ROWS];
__device__ int g_spill_n;

// ---------------- bucketed gather path ----------------

__global__ void zero_kernel(int nseg) {
    int i = blockIdx.x * blockDim.x + threadIdx.x;
    int stride = gridDim.x * blockDim.x;
    for (; i < nseg; i += stride) g_counts[i] = 0;
    if (blockIdx.x == 0 && threadIdx.x == 0) g_spill_n = 0;
}

__global__ void fill_kernel(const int4* __restrict__ vt_map4, int n_rows4, int vt_out) {
    int i = blockIdx.x * blockDim.x + threadIdx.x;
    if (i >= n_rows4) return;
    int4 m = __ldg(&vt_map4[i]);
    int rows[4] = {4 * i, 4 * i + 1, 4 * i + 2, 4 * i + 3};
    int segs[4] = {m.x, m.y, m.z, m.w};
    #pragma unroll
    for (int k = 0; k < 4; k++) {
        int seg = segs[k];
        if (seg < 0 || seg >= vt_out) continue;
        int pos = atomicAdd(&g_counts[seg], 1);
        if (pos < CAP) {
            g_bucket[(size_t)seg * CAP + pos] = rows[k];
        } else {
            int s = atomicAdd(&g_spill_n, 1);
            g_spill_rows[s] = rows[k];
        }
    }
}

__device__ __forceinline__ void spill_scan(float2& acc, int seg, int lane,
                                           const float2* __restrict__ in2,
                                           const int* __restrict__ vt_map) {
    int sn = g_spill_n;
    for (int e = 0; e < sn; e++) {
        int row = g_spill_rows[e];
        if (__ldg(&vt_map[row]) == seg) {
            float2 a = __ldg(&in2[(size_t)row * 32 + lane]);
            acc.x = fmaxf(acc.x, a.x);
            acc.y = fmaxf(acc.y, a.y);
        }
    }
}

// One warp per FOUR segments; C == 64: lane holds channels {2l, 2l+1} (float2).
// All 16 row loads per iteration are issued before any max consumes them.
__global__ void gather_max_kernel(const float2* __restrict__ in2,
                                  const int* __restrict__ vt_map,
                                  float2* __restrict__ out2, int nseg) {
    int warp = (blockIdx.x * blockDim.x + threadIdx.x) >> 5;
    int lane = threadIdx.x & 31;
    int s0 = 4 * warp;
    if (s0 >= nseg) return;
    bool full4 = (s0 + 3 < nseg);

    int4 cnt4;
    if (full4) {
        cnt4 = __ldg((const int4*)(g_counts + s0));
    } else {
        cnt4.x = __ldg(&g_counts[s0]);
        cnt4.y = (s0 + 1 < nseg) ? __ldg(&g_counts[s0 + 1]) : 0;
        cnt4.z = (s0 + 2 < nseg) ? __ldg(&g_counts[s0 + 2]) : 0;
        cnt4.w = 0;
    }
    int cnt[4] = {cnt4.x, cnt4.y, cnt4.z, cnt4.w};
    int use[4];
    #pragma unroll
    for (int k = 0; k < 4; k++) use[k] = cnt[k] < CAP ? cnt[k] : CAP;

    float2 acc[4];
    const float2 ninf2 = make_float2(NEG_INF, NEG_INF);
    #pragma unroll
    for (int k = 0; k < 4; k++) acc[k] = ninf2;

    int usemax = max(max(use[0], use[1]), max(use[2], use[3]));
    for (int j = 0; j < usemax; j += 4) {
        int4 idx[4];
        #pragma unroll
        for (int k = 0; k < 4; k++)
            idx[k] = (j < use[k])
                ? __ldg((const int4*)(g_bucket + (size_t)(s0 + k) * CAP + j))
                : make_int4(0, 0, 0, 0);

        // Issue all 16 row loads first (predicated; NEG_INF = max identity).
        float2 v[4][4];
        #pragma unroll
        for (int k = 0; k < 4; k++) {
            v[k][0] = (j + 0 < use[k]) ? __ldg(&in2[(size_t)idx[k].x * 32 + lane]) : ninf2;
            v[k][1] = (j + 1 < use[k]) ? __ldg(&in2[(size_t)idx[k].y * 32 + lane]) : ninf2;
            v[k][2] = (j + 2 < use[k]) ? __ldg(&in2[(size_t)idx[k].z * 32 + lane]) : ninf2;
            v[k][3] = (j + 3 < use[k]) ? __ldg(&in2[(size_t)idx[k].w * 32 + lane]) : ninf2;
        }
        #pragma unroll
        for (int k = 0; k < 4; k++) {
            acc[k].x = fmaxf(fmaxf(acc[k].x, fmaxf(v[k][0].x, v[k][1].x)),
                             fmaxf(v[k][2].x, v[k][3].x));
            acc[k].y = fmaxf(fmaxf(acc[k].y, fmaxf(v[k][0].y, v[k][1].y)),
                             fmaxf(v[k][2].y, v[k][3].y));
        }
    }

    #pragma unroll
    for (int k = 0; k < 4; k++)
        if (cnt[k] > CAP) spill_scan(acc[k], s0 + k, lane, in2, vt_map);  // ~never

    #pragma unroll
    for (int k = 0; k < 4; k++) {
        if (cnt[k] == 0) acc[k] = make_float2(0.0f, 0.0f);
        if (s0 + k < nseg) out2[(size_t)(s0 + k) * 32 + lane] = acc[k];
    }
}

// ---------------- fallback scatter path (generic) ----------------

__device__ __forceinline__ unsigned fkey(float f) {
    unsigned b = __float_as_uint(f);
    return (b & 0x80000000u) ? ~b : (b | 0x80000000u);
}
__device__ __forceinline__ float fdecode(unsigned k) {
    unsigned b = (k & 0x80000000u) ? (k & 0x7FFFFFFFu) : ~k;
    return __uint_as_float(b);
}
#define INIT_KEY 0x007FFFFFu

__global__ void init_out_kernel(unsigned* out, long n) {
    long i = blockIdx.x * (long)blockDim.x + threadIdx.x;
    long stride = gridDim.x * (long)blockDim.x;
    for (; i < n; i += stride) out[i] = INIT_KEY;
}

__global__ void scatter_max_kernel(const float* __restrict__ in,
                                   const int* __restrict__ vt_map,
                                   unsigned* __restrict__ out,
                                   long n_total, int C, int vt_out) {
    long i = blockIdx.x * (long)blockDim.x + threadIdx.x;
    long stride = gridDim.x * (long)blockDim.x;
    for (; i < n_total; i += stride) {
        long row = i / C;
        int  c   = (int)(i - row * C);
        int seg = vt_map[row];
        if (seg < 0 || seg >= vt_out) continue;
        atomicMax(out + (size_t)seg * C + c, fkey(in[i]));
    }
}

__global__ void fixup_kernel(unsigned* __restrict__ out, long n) {
    long i = blockIdx.x * (long)blockDim.x + threadIdx.x;
    long stride = gridDim.x * (long)blockDim.x;
    for (; i < n; i += stride) {
        unsigned k = out[i];
        float f = (k == INIT_KEY) ? 0.0f : fdecode(k);
        out[i] = __float_as_uint(f);
    }
}

// ---------------- launcher ----------------

extern "C" void kernel_launch(void* const* d_in, const int* in_sizes, int n_in,
                              void* d_out, int out_size) {
    const float* inputs = (const float*)d_in[0];
    // d_in[1] = vt_replace (unused for max pooling)
    const int*   vt_map = (const int*)d_in[2];

    long n_in_elems = in_sizes[0];                 // N_IN * C
    int  n_rows     = in_sizes[2];                 // N_IN
    int  C          = (int)(n_in_elems / n_rows);  // 64
    int  vt_out     = out_size / C;                // 262144

    const int TPB = 256;

    if (C == 64 && vt_out <= MAX_SEG && n_rows <= MAX_ROWS && (n_rows % 4) == 0) {
        int nseg = vt_out;
        int n_rows4 = n_rows / 4;

        zero_kernel<<<512, TPB>>>(nseg);
        fill_kernel<<<(n_rows4 + TPB - 1) / TPB, TPB>>>((const int4*)vt_map,
                                                        n_rows4, vt_out);

        int warps_per_block = TPB / 32;                 // 8 warps -> 32 segs/block
        int segs_per_block = warps_per_block * 4;
        int gblocks = (nseg + segs_per_block - 1) / segs_per_block;
        gather_max_kernel<<<gblocks, TPB>>>((const float2*)inputs, vt_map,
                                            (float2*)d_out, nseg);
    } else {
        long out_elems = (long)out_size;
        int blocks = 148 * 16;
        init_out_kernel<<<blocks, TPB>>>((unsigned*)d_out, out_elems);
        scatter_max_kernel<<<blocks * 2, TPB>>>(inputs, vt_map,
                                                (unsigned*)d_out, n_in_elems, C, vt_out);
        fixup_kernel<<<blocks, TPB>>>((unsigned*)d_out, out_elems);
    }
}